// round 9
// baseline (speedup 1.0000x reference)
#include <cuda_runtime.h>
#include <cuda_bf16.h>
#include <math.h>
#include <stdint.h>

// Problem constants
#define Bb 16
#define Ll 128
#define Dd 512
#define Ff 1024
#define Mm 2048

// -------- device scratch (proven safe footprint) --------
__device__ __align__(16) float g_c1[Ll*16];
__device__ __align__(16) float g_c2[Ll*16];
__device__ __align__(16) float g_c3[Ll*16];
__device__ __align__(16) float g_Gg[256*Ff];
__device__ __align__(16) float g_Gu[256*Ff];
__device__ __align__(16) float g_Gd[256*Dd];
__device__ __align__(16) float g_ing[Ll*Ff];
__device__ __align__(16) float g_inu[Ll*Ff];
__device__ __align__(16) float g_ind[Ll*Dd];
__device__ __align__(16) float g_U[Mm*Ff];
__device__ __align__(16) float g_V[Mm*Ff];
__device__ __align__(16) float g_H[Mm*Ff];
__device__ __align__(16) float g_O[Mm*Dd];

// ---------------- PTX helpers ----------------
__device__ __forceinline__ uint32_t smem_u32(const void* p) {
    uint32_t a;
    asm("{ .reg .u64 t; cvta.to.shared.u64 t, %1; cvt.u32.u64 %0, t; }" : "=r"(a) : "l"(p));
    return a;
}
__device__ __forceinline__ void ldsm4(uint32_t* r, uint32_t addr) {
    asm volatile("ldmatrix.sync.aligned.m8n8.x4.shared.b16 {%0,%1,%2,%3}, [%4];"
        : "=r"(r[0]), "=r"(r[1]), "=r"(r[2]), "=r"(r[3]) : "r"(addr));
}
__device__ __forceinline__ void ldsm4t(uint32_t* r, uint32_t addr) {
    asm volatile("ldmatrix.sync.aligned.m8n8.x4.trans.shared.b16 {%0,%1,%2,%3}, [%4];"
        : "=r"(r[0]), "=r"(r[1]), "=r"(r[2]), "=r"(r[3]) : "r"(addr));
}
__device__ __forceinline__ void mma16816(float* c, const uint32_t* a, const uint32_t* b) {
    asm volatile("mma.sync.aligned.m16n8k16.row.col.f32.bf16.bf16.f32 "
        "{%0,%1,%2,%3}, {%4,%5,%6,%7}, {%8,%9}, {%0,%1,%2,%3};"
        : "+f"(c[0]), "+f"(c[1]), "+f"(c[2]), "+f"(c[3])
        : "r"(a[0]), "r"(a[1]), "r"(a[2]), "r"(a[3]), "r"(b[0]), "r"(b[1]));
}
__device__ __forceinline__ void sts16(uint32_t addr, uint4 v) {
    asm volatile("st.shared.v4.b32 [%0], {%1,%2,%3,%4};" ::
        "r"(addr), "r"(v.x), "r"(v.y), "r"(v.z), "r"(v.w) : "memory");
}
__device__ __forceinline__ void sts8(uint32_t addr, uint32_t x, uint32_t y) {
    asm volatile("st.shared.v2.b32 [%0], {%1,%2};" :: "r"(addr), "r"(x), "r"(y) : "memory");
}

// split float4 -> 4 bf16 hi (8B) + 4 bf16 lo (8B)
__device__ __forceinline__ void cvt_store4(float4 v, uint32_t hiAddr, uint32_t loAddr) {
    __nv_bfloat162 h0 = __float22bfloat162_rn(make_float2(v.x, v.y));
    __nv_bfloat162 h1 = __float22bfloat162_rn(make_float2(v.z, v.w));
    float2 f0 = __bfloat1622float2(h0);
    float2 f1 = __bfloat1622float2(h1);
    __nv_bfloat162 l0 = __float22bfloat162_rn(make_float2(v.x - f0.x, v.y - f0.y));
    __nv_bfloat162 l1 = __float22bfloat162_rn(make_float2(v.z - f1.x, v.w - f1.y));
    sts8(hiAddr, *(uint32_t*)&h0, *(uint32_t*)&h1);
    sts8(loAddr, *(uint32_t*)&l0, *(uint32_t*)&l1);
}
// scaled variant for A (8 floats -> 16B hi + 16B lo)
__device__ __forceinline__ void cvt_store8s(float4 va, float4 vb, float sc,
                                            uint32_t hiAddr, uint32_t loAddr) {
    va.x *= sc; va.y *= sc; va.z *= sc; va.w *= sc;
    vb.x *= sc; vb.y *= sc; vb.z *= sc; vb.w *= sc;
    __nv_bfloat162 h0 = __float22bfloat162_rn(make_float2(va.x, va.y));
    __nv_bfloat162 h1 = __float22bfloat162_rn(make_float2(va.z, va.w));
    __nv_bfloat162 h2 = __float22bfloat162_rn(make_float2(vb.x, vb.y));
    __nv_bfloat162 h3 = __float22bfloat162_rn(make_float2(vb.z, vb.w));
    float2 f0 = __bfloat1622float2(h0);
    float2 f1 = __bfloat1622float2(h1);
    float2 f2 = __bfloat1622float2(h2);
    float2 f3 = __bfloat1622float2(h3);
    __nv_bfloat162 l0 = __float22bfloat162_rn(make_float2(va.x - f0.x, va.y - f0.y));
    __nv_bfloat162 l1 = __float22bfloat162_rn(make_float2(va.z - f1.x, va.w - f1.y));
    __nv_bfloat162 l2 = __float22bfloat162_rn(make_float2(vb.x - f2.x, vb.y - f2.y));
    __nv_bfloat162 l3 = __float22bfloat162_rn(make_float2(vb.z - f3.x, vb.w - f3.y));
    sts16(hiAddr, make_uint4(*(uint32_t*)&h0, *(uint32_t*)&h1, *(uint32_t*)&h2, *(uint32_t*)&h3));
    sts16(loAddr, make_uint4(*(uint32_t*)&l0, *(uint32_t*)&l1, *(uint32_t*)&l2, *(uint32_t*)&l3));
}

// ---------------- softmax ----------------
__global__ void softmax_kernel(const float* __restrict__ t1,
                               const float* __restrict__ t2,
                               const float* __restrict__ t3) {
    const float* src = (blockIdx.x == 0) ? t1 : (blockIdx.x == 1) ? t2 : t3;
    float* dst = (blockIdx.x == 0) ? g_c1 : (blockIdx.x == 1) ? g_c2 : g_c3;
    int l = threadIdx.x;
    float v[16];
    float mx = -1e30f;
#pragma unroll
    for (int k = 0; k < 16; k++) { v[k] = src[l*16 + k]; mx = fmaxf(mx, v[k]); }
    float s = 0.f;
#pragma unroll
    for (int k = 0; k < 16; k++) { v[k] = expf(v[k] - mx); s += v[k]; }
    float inv = 1.f / s;
#pragma unroll
    for (int k = 0; k < 16; k++) dst[l*16 + k] = v[k] * inv;
}

// ---------------- Gram ----------------
__global__ void gram_kernel(const float* __restrict__ Wg,
                            const float* __restrict__ Wu,
                            const float* __restrict__ Wd) {
    int w = blockIdx.y;
    const float* W; float* G; int R, C;
    if (w == 0)      { W = Wg; G = g_Gg; R = Dd; C = Ff; }
    else if (w == 1) { W = Wu; G = g_Gu; R = Dd; C = Ff; }
    else             { W = Wd; G = g_Gd; R = Ff; C = Dd; }
    int c0 = blockIdx.x * 32;
    if (c0 >= C) return;

    __shared__ __align__(16) float s[16][8][32];
    int t = threadIdx.x;
    int cc = t & 31;
    int pg = t >> 5;
    float acc[32];
#pragma unroll
    for (int i = 0; i < 32; i++) acc[i] = 0.f;

    for (int r0 = 0; r0 < R; r0 += 8) {
        __syncthreads();
#pragma unroll
        for (int j = 0; j < 16; j++) {
            int idx = j * 256 + t;
            int lc = idx & 31, rr = (idx >> 5) & 7, k = idx >> 8;
            s[k][rr][lc] = W[(size_t)k * R * C + (size_t)(r0 + rr) * C + c0 + lc];
        }
        __syncthreads();
#pragma unroll
        for (int rr = 0; rr < 8; rr++) {
            float wv[16];
#pragma unroll
            for (int k = 0; k < 16; k++) wv[k] = s[k][rr][cc];
            float a0 = s[(pg << 1) + 0][rr][cc];
            float a1 = s[(pg << 1) + 1][rr][cc];
#pragma unroll
            for (int pp = 0; pp < 16; pp++) acc[pp]      += a0 * wv[pp];
#pragma unroll
            for (int pp = 0; pp < 16; pp++) acc[16 + pp] += a1 * wv[pp];
        }
    }
#pragma unroll
    for (int pp = 0; pp < 32; pp++) {
        int p = ((pg << 1) + (pp >> 4)) * 16 + (pp & 15);
        G[(size_t)p * C + c0 + cc] = acc[pp];
    }
}

// ---------------- inverse norms: 8 tokens per block ----------------
__global__ void norm_kernel() {
    int w = blockIdx.z;
    int l0 = blockIdx.y * 8;
    const float* G; const float* coef; float* out; int C;
    if (w == 0)      { G = g_Gg; coef = g_c1; out = g_ing; C = Ff; }
    else if (w == 1) { G = g_Gu; coef = g_c2; out = g_inu; C = Ff; }
    else             { G = g_Gd; coef = g_c3; out = g_ind; C = Dd; }
    int c = blockIdx.x * 128 + threadIdx.x;
    if (c >= C) return;   // guard: down plane has C=512

    __shared__ float w2[8][256];
#pragma unroll
    for (int i = 0; i < 16; i++) {
        int idx = threadIdx.x * 16 + i;
        int li = idx >> 8, p = idx & 255;
        w2[li][p] = coef[(l0 + li) * 16 + (p >> 4)] * coef[(l0 + li) * 16 + (p & 15)];
    }
    __syncthreads();

    float acc[8];
#pragma unroll
    for (int i = 0; i < 8; i++) acc[i] = 0.f;
#pragma unroll 4
    for (int p = 0; p < 256; p++) {
        float g = G[(size_t)p * C + c];
#pragma unroll
        for (int i = 0; i < 8; i++) acc[i] += w2[i][p] * g;
    }
#pragma unroll
    for (int i = 0; i < 8; i++)
        out[(l0 + i) * C + c] = 1.f / fmaxf(sqrtf(fmaxf(acc[i], 0.f)), 1e-12f);
}

// ---------------- split-bf16 HMMA GEMM: single buffer, BK=32, 2 CTAs/SM ----------------
// which==0: blockIdx.z = 0 -> U (c1 . x)@Wg, 1 -> V (c2 . x)@Wu.  which==1: O (c3 . h)@Wd.
// Bw viewed as [Ktot, N] row-major. BM=128, BK=32, 256 threads, 8 warps (2m x 4n).
// No register prefetch: live regs <= 128 so launch_bounds(256,2) gives 2 CTAs/SM,
// and cross-CTA interleaving hides LDG latency + sync stalls.
template<int BN>
__global__ void __launch_bounds__(256, 2) gemm5(
    const float* __restrict__ A0,
    const float* __restrict__ Bw0, const float* __restrict__ Bw1,
    int which, int Ka, int ksegShift, int Ktot, int Nglob)
{
    constexpr int WN = BN / 4;
    constexpr int NF = WN / 8;
    constexpr int AMB = 128 * 80;            // one A matrix (32 bf16 + pad) * 128 rows
    constexpr int BSTRIDE = BN * 2 + 16;     // 272 / 144
    constexpr int BMB = 32 * BSTRIDE;
    constexpr int QPT = (BN == 128 ? 4 : 2); // float4 per thread for B staging

    __shared__ __align__(128) char smem_raw[2 * AMB + 2 * BMB]; // 37888 / 29696
    uint32_t sA_hi = smem_u32(smem_raw);
    uint32_t sA_lo = sA_hi + AMB;
    uint32_t sB_hi = sA_hi + 2 * AMB;
    uint32_t sB_lo = sB_hi + BMB;

    const float* coef; float* Cout; const float* Ap; const float* Bw;
    if (which == 0) {
        Ap = A0;
        if (blockIdx.z == 0) { coef = g_c1; Bw = Bw0; Cout = g_U; }
        else                 { coef = g_c2; Bw = Bw1; Cout = g_V; }
    } else {
        Ap = g_H; coef = g_c3; Bw = Bw0; Cout = g_O;
    }

    int t = threadIdx.x, lane = t & 31, warp = t >> 5;
    int wm = warp & 1, wn = warp >> 1;
    int m0 = blockIdx.y * 128, n0 = blockIdx.x * BN;

    // A staging: 2 threads per row, 16 floats each
    int arow = t >> 1, ahalf = t & 1;
    const float* aRow = Ap + (size_t)(m0 + arow) * Ka + ahalf * 16;
    const float* crow = coef + ((m0 + arow) & 127) * 16;
    uint32_t aoff = (uint32_t)arow * 80 + ahalf * 32;

    // B staging: 8 threads per k-row (32 rows), QPT float4 each
    int krow = t >> 3;
    int bq = t & 7;
    const float* bRowBase = Bw + (size_t)krow * Nglob + n0 + bq * (QPT * 4);
    uint32_t boff = (uint32_t)krow * BSTRIDE + bq * (QPT * 8);

    float acc[4][NF][4];
#pragma unroll
    for (int f = 0; f < 4; f++)
#pragma unroll
        for (int g = 0; g < NF; g++)
#pragma unroll
            for (int j = 0; j < 4; j++) acc[f][g][j] = 0.f;

    int nit = Ktot >> 5;
    for (int it = 0; it < nit; it++) {
        int kt = it << 5;
        // ---- stage tile (load -> convert/split -> STS) ----
        {
            float sc = crow[kt >> ksegShift];
            const float* ar = aRow + (kt & (Ka - 1));
            float4 a0v = *(const float4*)(ar + 0);
            float4 a1v = *(const float4*)(ar + 4);
            float4 a2v = *(const float4*)(ar + 8);
            float4 a3v = *(const float4*)(ar + 12);
            cvt_store8s(a0v, a1v, sc, sA_hi + aoff,      sA_lo + aoff);
            cvt_store8s(a2v, a3v, sc, sA_hi + aoff + 16, sA_lo + aoff + 16);
            const float* br = bRowBase + (size_t)kt * Nglob;
#pragma unroll
            for (int j = 0; j < QPT; j++) {
                float4 bv = *(const float4*)(br + j * 4);
                cvt_store4(bv, sB_hi + boff + j * 8, sB_lo + boff + j * 8);
            }
        }
        __syncthreads();   // tile visible

        // ---- MMA: 2 k-steps of 16 ----
#pragma unroll
        for (int ks = 0; ks < 2; ks++) {
            uint32_t acolB = (uint32_t)ks * 32 + ((lane >> 4) & 1) * 16;
            uint32_t AH[4][4], AL[4][4];
#pragma unroll
            for (int f = 0; f < 4; f++) {
                uint32_t roff = (uint32_t)(wm * 64 + f * 16 + (lane & 15)) * 80 + acolB;
                ldsm4(AH[f], sA_hi + roff);
                ldsm4(AL[f], sA_lo + roff);
            }
            uint32_t BH[NF][2], BL[NF][2];
            uint32_t brow = (uint32_t)(ks * 16 + (lane & 15)) * BSTRIDE;
#pragma unroll
            for (int j = 0; j < NF / 2; j++) {
                uint32_t coff = (uint32_t)(wn * WN + j * 16 + ((lane >> 4) & 1) * 8) * 2;
                uint32_t r[4];
                ldsm4t(r, sB_hi + brow + coff);
                BH[2*j][0] = r[0]; BH[2*j][1] = r[1];
                BH[2*j+1][0] = r[2]; BH[2*j+1][1] = r[3];
                ldsm4t(r, sB_lo + brow + coff);
                BL[2*j][0] = r[0]; BL[2*j][1] = r[1];
                BL[2*j+1][0] = r[2]; BL[2*j+1][1] = r[3];
            }
#pragma unroll
            for (int f = 0; f < 4; f++)
#pragma unroll
                for (int g = 0; g < NF; g++) {
                    mma16816(acc[f][g], AH[f], BH[g]);
                    mma16816(acc[f][g], AL[f], BH[g]);
                    mma16816(acc[f][g], AH[f], BL[g]);
                }
        }
        __syncthreads();   // MMAs done before next store
    }

    // epilogue
#pragma unroll
    for (int f = 0; f < 4; f++) {
#pragma unroll
        for (int g = 0; g < NF; g++) {
            int r0 = m0 + wm * 64 + f * 16 + (lane >> 2);
            int col = n0 + wn * WN + g * 8 + (lane & 3) * 2;
            float* p = Cout + (size_t)r0 * Nglob + col;
            *(float2*)p = make_float2(acc[f][g][0], acc[f][g][1]);
            *(float2*)(p + 8 * (size_t)Nglob) = make_float2(acc[f][g][2], acc[f][g][3]);
        }
    }
}

// ---------------- elementwise h ----------------
__global__ void h_kernel(const float* __restrict__ usp, const float* __restrict__ vsp) {
    const float SQRT_D = 22.62741699796952f;
    int i4 = blockIdx.x * blockDim.x + threadIdx.x;
    if (i4 >= Mm * Ff / 4) return;
    int m  = i4 >> 8;
    int f  = (i4 & 255) * 4;
    int l  = m & 127;

    float4 u  = *(const float4*)(g_U   + (size_t)m * Ff + f);
    float4 v  = *(const float4*)(g_V   + (size_t)m * Ff + f);
    float4 ig = *(const float4*)(g_ing + (size_t)l * Ff + f);
    float4 iu = *(const float4*)(g_inu + (size_t)l * Ff + f);
    float4 us = *(const float4*)(usp + f);
    float4 vs = *(const float4*)(vsp + f);

    float4 h;
    { float uu = u.x * ig.x, vv = v.x * iu.x; float zz = fabsf(vs.x) * SQRT_D * vv;
      h.x = (zz / (1.f + expf(-zz))) * (fabsf(us.x) * uu); }
    { float uu = u.y * ig.y, vv = v.y * iu.y; float zz = fabsf(vs.y) * SQRT_D * vv;
      h.y = (zz / (1.f + expf(-zz))) * (fabsf(us.y) * uu); }
    { float uu = u.z * ig.z, vv = v.z * iu.z; float zz = fabsf(vs.z) * SQRT_D * vv;
      h.z = (zz / (1.f + expf(-zz))) * (fabsf(us.z) * uu); }
    { float uu = u.w * ig.w, vv = v.w * iu.w; float zz = fabsf(vs.w) * SQRT_D * vv;
      h.w = (zz / (1.f + expf(-zz))) * (fabsf(us.w) * uu); }
    *(float4*)(g_H + (size_t)m * Ff + f) = h;
}

// ---------------- final normalize ----------------
__global__ void out_kernel(float* __restrict__ out) {
    int m = blockIdx.x;
    int t = threadIdx.x;
    int l = m & 127;

    float4 o  = *(const float4*)(g_O   + (size_t)m * Dd + t * 4);
    float4 iv = *(const float4*)(g_ind + (size_t)l * Dd + t * 4);
    o.x *= iv.x; o.y *= iv.y; o.z *= iv.z; o.w *= iv.w;

    float ss = o.x*o.x + o.y*o.y + o.z*o.z + o.w*o.w;
#pragma unroll
    for (int off = 16; off > 0; off >>= 1)
        ss += __shfl_xor_sync(0xffffffffu, ss, off);

    __shared__ float ws[4];
    if ((t & 31) == 0) ws[t >> 5] = ss;
    __syncthreads();
    float tot = ws[0] + ws[1] + ws[2] + ws[3];
    float sc = 1.f / fmaxf(sqrtf(tot), 1e-12f);

    o.x *= sc; o.y *= sc; o.z *= sc; o.w *= sc;
    *(float4*)(out + (size_t)m * Dd + t * 4) = o;
}

// ---------------- launch ----------------
extern "C" void kernel_launch(void* const* d_in, const int* in_sizes, int n_in,
                              void* d_out, int out_size) {
    const float* x   = (const float*)d_in[0];
    const float* Wg  = (const float*)d_in[1];
    const float* Wu  = (const float*)d_in[2];
    const float* Wd  = (const float*)d_in[3];
    const float* t1  = (const float*)d_in[4];
    const float* t2  = (const float*)d_in[5];
    const float* t3  = (const float*)d_in[6];
    const float* usp = (const float*)d_in[7];
    const float* vsp = (const float*)d_in[8];
    float* out = (float*)d_out;

    softmax_kernel<<<3, 128>>>(t1, t2, t3);
    gram_kernel<<<dim3(32, 3), 256>>>(Wg, Wu, Wd);
    norm_kernel<<<dim3(8, 16, 3), 128>>>();

    // U and V fused (z=0 -> U, z=1 -> V), 256 blocks, 2 CTAs/SM
    gemm5<128><<<dim3(8, 16, 2), 256>>>(x, Wg, Wu, 0, 512, 9, 8192, 1024);
    // h = silu(vs*v) * (us*u)
    h_kernel<<<2048, 256>>>(usp, vsp);
    // O = (c3 . h) @ Wd
    gemm5<64><<<dim3(8, 16, 1), 256>>>(nullptr, Wd, nullptr, 1, 1024, 10, 16384, 512);
    // final
    out_kernel<<<2048, 128>>>(out);
}

// round 10
// speedup vs baseline: 1.2156x; 1.2156x over previous
#include <cuda_runtime.h>
#include <cuda_fp16.h>
#include <math.h>
#include <stdint.h>

// Problem constants
#define Bb 16
#define Ll 128
#define Dd 512
#define Ff 1024
#define Mm 2048

// -------- device scratch (proven safe footprint) --------
__device__ __align__(16) float g_c1[Ll*16];
__device__ __align__(16) float g_c2[Ll*16];
__device__ __align__(16) float g_c3[Ll*16];
__device__ __align__(16) float g_Gg[256*Ff];
__device__ __align__(16) float g_Gu[256*Ff];
__device__ __align__(16) float g_Gd[256*Dd];
__device__ __align__(16) float g_ing[Ll*Ff];
__device__ __align__(16) float g_inu[Ll*Ff];
__device__ __align__(16) float g_ind[Ll*Dd];
__device__ __align__(16) float g_U[Mm*Ff];
__device__ __align__(16) float g_V[Mm*Ff];
__device__ __align__(16) float g_H[Mm*Ff];
__device__ __align__(16) float g_O[Mm*Dd];

// ---------------- PTX helpers ----------------
__device__ __forceinline__ uint32_t smem_u32(const void* p) {
    uint32_t a;
    asm("{ .reg .u64 t; cvta.to.shared.u64 t, %1; cvt.u32.u64 %0, t; }" : "=r"(a) : "l"(p));
    return a;
}
__device__ __forceinline__ void ldsm4(uint32_t* r, uint32_t addr) {
    asm volatile("ldmatrix.sync.aligned.m8n8.x4.shared.b16 {%0,%1,%2,%3}, [%4];"
        : "=r"(r[0]), "=r"(r[1]), "=r"(r[2]), "=r"(r[3]) : "r"(addr));
}
__device__ __forceinline__ void ldsm4t(uint32_t* r, uint32_t addr) {
    asm volatile("ldmatrix.sync.aligned.m8n8.x4.trans.shared.b16 {%0,%1,%2,%3}, [%4];"
        : "=r"(r[0]), "=r"(r[1]), "=r"(r[2]), "=r"(r[3]) : "r"(addr));
}
__device__ __forceinline__ void mmaf16(float* c, const uint32_t* a, const uint32_t* b) {
    asm volatile("mma.sync.aligned.m16n8k16.row.col.f32.f16.f16.f32 "
        "{%0,%1,%2,%3}, {%4,%5,%6,%7}, {%8,%9}, {%0,%1,%2,%3};"
        : "+f"(c[0]), "+f"(c[1]), "+f"(c[2]), "+f"(c[3])
        : "r"(a[0]), "r"(a[1]), "r"(a[2]), "r"(a[3]), "r"(b[0]), "r"(b[1]));
}
__device__ __forceinline__ void sts16(uint32_t addr, uint4 v) {
    asm volatile("st.shared.v4.b32 [%0], {%1,%2,%3,%4};" ::
        "r"(addr), "r"(v.x), "r"(v.y), "r"(v.z), "r"(v.w) : "memory");
}
__device__ __forceinline__ void sts8(uint32_t addr, uint32_t x, uint32_t y) {
    asm volatile("st.shared.v2.b32 [%0], {%1,%2};" :: "r"(addr), "r"(x), "r"(y) : "memory");
}

// B: float4 -> 4 fp16 (8B), single matrix
__device__ __forceinline__ void cvtB_store4(float4 v, uint32_t addr) {
    __half2 h0 = __float22half2_rn(make_float2(v.x, v.y));
    __half2 h1 = __float22half2_rn(make_float2(v.z, v.w));
    sts8(addr, *(uint32_t*)&h0, *(uint32_t*)&h1);
}
// A: 8 scaled floats -> fp16 hi 16B + fp16 lo 16B
__device__ __forceinline__ void cvtA_store8(float4 va, float4 vb, float sc,
                                            uint32_t hiAddr, uint32_t loAddr) {
    va.x *= sc; va.y *= sc; va.z *= sc; va.w *= sc;
    vb.x *= sc; vb.y *= sc; vb.z *= sc; vb.w *= sc;
    __half2 h0 = __float22half2_rn(make_float2(va.x, va.y));
    __half2 h1 = __float22half2_rn(make_float2(va.z, va.w));
    __half2 h2 = __float22half2_rn(make_float2(vb.x, vb.y));
    __half2 h3 = __float22half2_rn(make_float2(vb.z, vb.w));
    float2 f0 = __half22float2(h0);
    float2 f1 = __half22float2(h1);
    float2 f2 = __half22float2(h2);
    float2 f3 = __half22float2(h3);
    __half2 l0 = __float22half2_rn(make_float2(va.x - f0.x, va.y - f0.y));
    __half2 l1 = __float22half2_rn(make_float2(va.z - f1.x, va.w - f1.y));
    __half2 l2 = __float22half2_rn(make_float2(vb.x - f2.x, vb.y - f2.y));
    __half2 l3 = __float22half2_rn(make_float2(vb.z - f3.x, vb.w - f3.y));
    sts16(hiAddr, make_uint4(*(uint32_t*)&h0, *(uint32_t*)&h1, *(uint32_t*)&h2, *(uint32_t*)&h3));
    sts16(loAddr, make_uint4(*(uint32_t*)&l0, *(uint32_t*)&l1, *(uint32_t*)&l2, *(uint32_t*)&l3));
}

// ---------------- softmax ----------------
__global__ void softmax_kernel(const float* __restrict__ t1,
                               const float* __restrict__ t2,
                               const float* __restrict__ t3) {
    const float* src = (blockIdx.x == 0) ? t1 : (blockIdx.x == 1) ? t2 : t3;
    float* dst = (blockIdx.x == 0) ? g_c1 : (blockIdx.x == 1) ? g_c2 : g_c3;
    int l = threadIdx.x;
    float v[16];
    float mx = -1e30f;
#pragma unroll
    for (int k = 0; k < 16; k++) { v[k] = src[l*16 + k]; mx = fmaxf(mx, v[k]); }
    float s = 0.f;
#pragma unroll
    for (int k = 0; k < 16; k++) { v[k] = expf(v[k] - mx); s += v[k]; }
    float inv = 1.f / s;
#pragma unroll
    for (int k = 0; k < 16; k++) dst[l*16 + k] = v[k] * inv;
}

// ---------------- Gram ----------------
__global__ void gram_kernel(const float* __restrict__ Wg,
                            const float* __restrict__ Wu,
                            const float* __restrict__ Wd) {
    int w = blockIdx.y;
    const float* W; float* G; int R, C;
    if (w == 0)      { W = Wg; G = g_Gg; R = Dd; C = Ff; }
    else if (w == 1) { W = Wu; G = g_Gu; R = Dd; C = Ff; }
    else             { W = Wd; G = g_Gd; R = Ff; C = Dd; }
    int c0 = blockIdx.x * 32;
    if (c0 >= C) return;

    __shared__ __align__(16) float s[16][8][32];
    int t = threadIdx.x;
    int cc = t & 31;
    int pg = t >> 5;
    float acc[32];
#pragma unroll
    for (int i = 0; i < 32; i++) acc[i] = 0.f;

    for (int r0 = 0; r0 < R; r0 += 8) {
        __syncthreads();
#pragma unroll
        for (int j = 0; j < 16; j++) {
            int idx = j * 256 + t;
            int lc = idx & 31, rr = (idx >> 5) & 7, k = idx >> 8;
            s[k][rr][lc] = W[(size_t)k * R * C + (size_t)(r0 + rr) * C + c0 + lc];
        }
        __syncthreads();
#pragma unroll
        for (int rr = 0; rr < 8; rr++) {
            float wv[16];
#pragma unroll
            for (int k = 0; k < 16; k++) wv[k] = s[k][rr][cc];
            float a0 = s[(pg << 1) + 0][rr][cc];
            float a1 = s[(pg << 1) + 1][rr][cc];
#pragma unroll
            for (int pp = 0; pp < 16; pp++) acc[pp]      += a0 * wv[pp];
#pragma unroll
            for (int pp = 0; pp < 16; pp++) acc[16 + pp] += a1 * wv[pp];
        }
    }
#pragma unroll
    for (int pp = 0; pp < 32; pp++) {
        int p = ((pg << 1) + (pp >> 4)) * 16 + (pp & 15);
        G[(size_t)p * C + c0 + cc] = acc[pp];
    }
}

// ---------------- inverse norms: 8 tokens per block ----------------
__global__ void norm_kernel() {
    int w = blockIdx.z;
    int l0 = blockIdx.y * 8;
    const float* G; const float* coef; float* out; int C;
    if (w == 0)      { G = g_Gg; coef = g_c1; out = g_ing; C = Ff; }
    else if (w == 1) { G = g_Gu; coef = g_c2; out = g_inu; C = Ff; }
    else             { G = g_Gd; coef = g_c3; out = g_ind; C = Dd; }
    int c = blockIdx.x * 128 + threadIdx.x;
    if (c >= C) return;   // guard: down plane has C=512

    __shared__ float w2[8][256];
#pragma unroll
    for (int i = 0; i < 16; i++) {
        int idx = threadIdx.x * 16 + i;
        int li = idx >> 8, p = idx & 255;
        w2[li][p] = coef[(l0 + li) * 16 + (p >> 4)] * coef[(l0 + li) * 16 + (p & 15)];
    }
    __syncthreads();

    float acc[8];
#pragma unroll
    for (int i = 0; i < 8; i++) acc[i] = 0.f;
#pragma unroll 4
    for (int p = 0; p < 256; p++) {
        float g = G[(size_t)p * C + c];
#pragma unroll
        for (int i = 0; i < 8; i++) acc[i] += w2[i][p] * g;
    }
#pragma unroll
    for (int i = 0; i < 8; i++)
        out[(l0 + i) * C + c] = 1.f / fmaxf(sqrtf(fmaxf(acc[i], 0.f)), 1e-12f);
}

// ---------------- fp16 2-MMA HMMA GEMM (A split hi/lo, B single) ----------------
// C[M=2048, Nglob] = A_eff @ Bw.  A_eff[m, kseg*Ka+d] = coef[(m&127)*16+kseg]*A[m,d].
// which==0: z=0 -> U (c1,x,Wg), z=1 -> V (c2,x,Wu). which==1: O (c3,h,Wd).
// Bw = fp32 weight basis viewed as [Ktot, N] row-major.
// BM=128, BK=32, 256 threads, 8 warps (2m x 4n), warp tile 64 x (BN/4).
template<int BN>
__global__ void __launch_bounds__(256, 1) gemm6(
    const float* __restrict__ A0,
    const float* __restrict__ Bw0, const float* __restrict__ Bw1,
    int which, int Ka, int ksegShift, int Ktot, int Nglob)
{
    constexpr int WN = BN / 4;               // 64 / 16
    constexpr int NF = WN / 8;               // 8 / 2
    constexpr int AMB = 128 * 80;            // one A matrix (32 fp16 + pad)
    constexpr int BSTRIDE = BN * 2 + 16;     // 528 / 144
    constexpr int BMB = 32 * BSTRIDE;        // 16896 / 4608
    constexpr int QPT4 = BN / 32;            // float4 per thread for B (8 / 2)

    __shared__ __align__(128) char smem_raw[2 * AMB + BMB]; // 37376 / 25088
    uint32_t sA_hi = smem_u32(smem_raw);
    uint32_t sA_lo = sA_hi + AMB;
    uint32_t sB    = sA_hi + 2 * AMB;

    const float* coef; float* Cout; const float* Ap; const float* Bw;
    if (which == 0) {
        Ap = A0;
        if (blockIdx.z == 0) { coef = g_c1; Bw = Bw0; Cout = g_U; }
        else                 { coef = g_c2; Bw = Bw1; Cout = g_V; }
    } else {
        Ap = g_H; coef = g_c3; Bw = Bw0; Cout = g_O;
    }

    int t = threadIdx.x, lane = t & 31, warp = t >> 5;
    int wm = warp & 1, wn = warp >> 1;
    int m0 = blockIdx.y * 128, n0 = blockIdx.x * BN;

    // A staging: 2 threads per row, 16 floats each
    int arow = t >> 1, ahalf = t & 1;
    const float* aRow = Ap + (size_t)(m0 + arow) * Ka + ahalf * 16;
    const float* crow = coef + ((m0 + arow) & 127) * 16;
    uint32_t aoff = (uint32_t)arow * 80 + ahalf * 32;

    // B staging: 8 threads per k-row (32 rows), QPT4 float4 each, coalesced
    int krow = t >> 3;
    int bq = t & 7;
    const float* bRowBase = Bw + (size_t)krow * Nglob + n0;
    uint32_t bRowOff = (uint32_t)krow * BSTRIDE;

    float acc[4][NF][4];
#pragma unroll
    for (int f = 0; f < 4; f++)
#pragma unroll
        for (int g = 0; g < NF; g++)
#pragma unroll
            for (int j = 0; j < 4; j++) acc[f][g][j] = 0.f;

    int nit = Ktot >> 5;
    for (int it = 0; it < nit; it++) {
        int kt = it << 5;
        // ---- stage tile ----
        {
            float sc = crow[kt >> ksegShift];
            const float* ar = aRow + (kt & (Ka - 1));
            float4 a0v = *(const float4*)(ar + 0);
            float4 a1v = *(const float4*)(ar + 4);
            float4 a2v = *(const float4*)(ar + 8);
            float4 a3v = *(const float4*)(ar + 12);
            cvtA_store8(a0v, a1v, sc, sA_hi + aoff,      sA_lo + aoff);
            cvtA_store8(a2v, a3v, sc, sA_hi + aoff + 16, sA_lo + aoff + 16);
            const float* br = bRowBase + (size_t)kt * Nglob;
#pragma unroll
            for (int j = 0; j < QPT4; j++) {
                int c4 = bq + 8 * j;                 // coalesced across threads
                float4 bv = *(const float4*)(br + c4 * 4);
                cvtB_store4(bv, sB + bRowOff + c4 * 8);
            }
        }
        __syncthreads();

        // ---- MMA: 2 k-steps of 16 ----
#pragma unroll
        for (int ks = 0; ks < 2; ks++) {
            // B fragments first (single matrix)
            uint32_t BF[NF][2];
            uint32_t brow = (uint32_t)(ks * 16 + (lane & 15)) * BSTRIDE;
#pragma unroll
            for (int j = 0; j < NF / 2; j++) {
                uint32_t coff = (uint32_t)(wn * WN + j * 16 + ((lane >> 4) & 1) * 8) * 2;
                uint32_t r[4];
                ldsm4t(r, sB + brow + coff);
                BF[2*j][0] = r[0]; BF[2*j][1] = r[1];
                BF[2*j+1][0] = r[2]; BF[2*j+1][1] = r[3];
            }
            uint32_t acolB = (uint32_t)ks * 32 + ((lane >> 4) & 1) * 16;
            // A-hi pass
            {
                uint32_t AF[4][4];
#pragma unroll
                for (int f = 0; f < 4; f++) {
                    uint32_t roff = (uint32_t)(wm * 64 + f * 16 + (lane & 15)) * 80 + acolB;
                    ldsm4(AF[f], sA_hi + roff);
                }
#pragma unroll
                for (int f = 0; f < 4; f++)
#pragma unroll
                    for (int g = 0; g < NF; g++)
                        mmaf16(acc[f][g], AF[f], BF[g]);
            }
            // A-lo pass (reuses frag registers)
            {
                uint32_t AF[4][4];
#pragma unroll
                for (int f = 0; f < 4; f++) {
                    uint32_t roff = (uint32_t)(wm * 64 + f * 16 + (lane & 15)) * 80 + acolB;
                    ldsm4(AF[f], sA_lo + roff);
                }
#pragma unroll
                for (int f = 0; f < 4; f++)
#pragma unroll
                    for (int g = 0; g < NF; g++)
                        mmaf16(acc[f][g], AF[f], BF[g]);
            }
        }
        __syncthreads();
    }

    // epilogue
#pragma unroll
    for (int f = 0; f < 4; f++) {
#pragma unroll
        for (int g = 0; g < NF; g++) {
            int r0 = m0 + wm * 64 + f * 16 + (lane >> 2);
            int col = n0 + wn * WN + g * 8 + (lane & 3) * 2;
            float* p = Cout + (size_t)r0 * Nglob + col;
            *(float2*)p = make_float2(acc[f][g][0], acc[f][g][1]);
            *(float2*)(p + 8 * (size_t)Nglob) = make_float2(acc[f][g][2], acc[f][g][3]);
        }
    }
}

// ---------------- elementwise h ----------------
__global__ void h_kernel(const float* __restrict__ usp, const float* __restrict__ vsp) {
    const float SQRT_D = 22.62741699796952f;
    int i4 = blockIdx.x * blockDim.x + threadIdx.x;
    if (i4 >= Mm * Ff / 4) return;
    int m  = i4 >> 8;
    int f  = (i4 & 255) * 4;
    int l  = m & 127;

    float4 u  = *(const float4*)(g_U   + (size_t)m * Ff + f);
    float4 v  = *(const float4*)(g_V   + (size_t)m * Ff + f);
    float4 ig = *(const float4*)(g_ing + (size_t)l * Ff + f);
    float4 iu = *(const float4*)(g_inu + (size_t)l * Ff + f);
    float4 us = *(const float4*)(usp + f);
    float4 vs = *(const float4*)(vsp + f);

    float4 h;
    { float uu = u.x * ig.x, vv = v.x * iu.x; float zz = fabsf(vs.x) * SQRT_D * vv;
      h.x = (zz / (1.f + expf(-zz))) * (fabsf(us.x) * uu); }
    { float uu = u.y * ig.y, vv = v.y * iu.y; float zz = fabsf(vs.y) * SQRT_D * vv;
      h.y = (zz / (1.f + expf(-zz))) * (fabsf(us.y) * uu); }
    { float uu = u.z * ig.z, vv = v.z * iu.z; float zz = fabsf(vs.z) * SQRT_D * vv;
      h.z = (zz / (1.f + expf(-zz))) * (fabsf(us.z) * uu); }
    { float uu = u.w * ig.w, vv = v.w * iu.w; float zz = fabsf(vs.w) * SQRT_D * vv;
      h.w = (zz / (1.f + expf(-zz))) * (fabsf(us.w) * uu); }
    *(float4*)(g_H + (size_t)m * Ff + f) = h;
}

// ---------------- final normalize ----------------
__global__ void out_kernel(float* __restrict__ out) {
    int m = blockIdx.x;
    int t = threadIdx.x;
    int l = m & 127;

    float4 o  = *(const float4*)(g_O   + (size_t)m * Dd + t * 4);
    float4 iv = *(const float4*)(g_ind + (size_t)l * Dd + t * 4);
    o.x *= iv.x; o.y *= iv.y; o.z *= iv.z; o.w *= iv.w;

    float ss = o.x*o.x + o.y*o.y + o.z*o.z + o.w*o.w;
#pragma unroll
    for (int off = 16; off > 0; off >>= 1)
        ss += __shfl_xor_sync(0xffffffffu, ss, off);

    __shared__ float ws[4];
    if ((t & 31) == 0) ws[t >> 5] = ss;
    __syncthreads();
    float tot = ws[0] + ws[1] + ws[2] + ws[3];
    float sc = 1.f / fmaxf(sqrtf(tot), 1e-12f);

    o.x *= sc; o.y *= sc; o.z *= sc; o.w *= sc;
    *(float4*)(out + (size_t)m * Dd + t * 4) = o;
}

// ---------------- launch ----------------
extern "C" void kernel_launch(void* const* d_in, const int* in_sizes, int n_in,
                              void* d_out, int out_size) {
    const float* x   = (const float*)d_in[0];
    const float* Wg  = (const float*)d_in[1];
    const float* Wu  = (const float*)d_in[2];
    const float* Wd  = (const float*)d_in[3];
    const float* t1  = (const float*)d_in[4];
    const float* t2  = (const float*)d_in[5];
    const float* t3  = (const float*)d_in[6];
    const float* usp = (const float*)d_in[7];
    const float* vsp = (const float*)d_in[8];
    float* out = (float*)d_out;

    softmax_kernel<<<3, 128>>>(t1, t2, t3);
    gram_kernel<<<dim3(32, 3), 256>>>(Wg, Wu, Wd);
    norm_kernel<<<dim3(8, 16, 3), 128>>>();

    // U and V fused (z=0 -> U, z=1 -> V): BN=256, 128 blocks
    gemm6<256><<<dim3(4, 16, 2), 256>>>(x, Wg, Wu, 0, 512, 9, 8192, 1024);
    // h = silu(vs*v) * (us*u)
    h_kernel<<<2048, 256>>>(usp, vsp);
    // O = (c3 . h) @ Wd: BN=64, 128 blocks
    gemm6<64><<<dim3(8, 16, 1), 256>>>(nullptr, Wd, nullptr, 1, 1024, 10, 16384, 512);
    // final
    out_kernel<<<2048, 128>>>(out);
}

// round 11
// speedup vs baseline: 1.6939x; 1.3935x over previous
#include <cuda_runtime.h>
#include <cuda_fp16.h>
#include <math.h>
#include <stdint.h>

// Problem constants
#define Bb 16
#define Ll 128
#define Dd 512
#define Ff 1024
#define Mm 2048

// -------- device scratch (proven safe footprint) --------
__device__ __align__(16) float g_c1[Ll*16];
__device__ __align__(16) float g_c2[Ll*16];
__device__ __align__(16) float g_c3[Ll*16];
__device__ __align__(16) float g_Gg[256*Ff];
__device__ __align__(16) float g_Gu[256*Ff];
__device__ __align__(16) float g_Gd[256*Dd];
__device__ __align__(16) float g_ing[Ll*Ff];
__device__ __align__(16) float g_inu[Ll*Ff];
__device__ __align__(16) float g_ind[Ll*Dd];
__device__ __align__(16) float g_U[Mm*Ff];
__device__ __align__(16) float g_V[Mm*Ff];
__device__ __align__(16) float g_H[Mm*Ff];
__device__ __align__(16) float g_O[Mm*Dd];

// ---------------- PTX helpers ----------------
__device__ __forceinline__ uint32_t smem_u32(const void* p) {
    uint32_t a;
    asm("{ .reg .u64 t; cvta.to.shared.u64 t, %1; cvt.u32.u64 %0, t; }" : "=r"(a) : "l"(p));
    return a;
}
__device__ __forceinline__ void ldsm4(uint32_t* r, uint32_t addr) {
    asm volatile("ldmatrix.sync.aligned.m8n8.x4.shared.b16 {%0,%1,%2,%3}, [%4];"
        : "=r"(r[0]), "=r"(r[1]), "=r"(r[2]), "=r"(r[3]) : "r"(addr));
}
__device__ __forceinline__ void ldsm4t(uint32_t* r, uint32_t addr) {
    asm volatile("ldmatrix.sync.aligned.m8n8.x4.trans.shared.b16 {%0,%1,%2,%3}, [%4];"
        : "=r"(r[0]), "=r"(r[1]), "=r"(r[2]), "=r"(r[3]) : "r"(addr));
}
__device__ __forceinline__ void mmaf16(float* c, const uint32_t* a, const uint32_t* b) {
    asm volatile("mma.sync.aligned.m16n8k16.row.col.f32.f16.f16.f32 "
        "{%0,%1,%2,%3}, {%4,%5,%6,%7}, {%8,%9}, {%0,%1,%2,%3};"
        : "+f"(c[0]), "+f"(c[1]), "+f"(c[2]), "+f"(c[3])
        : "r"(a[0]), "r"(a[1]), "r"(a[2]), "r"(a[3]), "r"(b[0]), "r"(b[1]));
}
__device__ __forceinline__ void sts16(uint32_t addr, uint4 v) {
    asm volatile("st.shared.v4.b32 [%0], {%1,%2,%3,%4};" ::
        "r"(addr), "r"(v.x), "r"(v.y), "r"(v.z), "r"(v.w) : "memory");
}
__device__ __forceinline__ void sts8(uint32_t addr, uint32_t x, uint32_t y) {
    asm volatile("st.shared.v2.b32 [%0], {%1,%2};" :: "r"(addr), "r"(x), "r"(y) : "memory");
}

// B: float4 -> 4 fp16 (8B), single matrix
__device__ __forceinline__ void cvtB_store4(float4 v, uint32_t addr) {
    __half2 h0 = __float22half2_rn(make_float2(v.x, v.y));
    __half2 h1 = __float22half2_rn(make_float2(v.z, v.w));
    sts8(addr, *(uint32_t*)&h0, *(uint32_t*)&h1);
}
// A: 8 scaled floats -> fp16 hi 16B + fp16 lo 16B
__device__ __forceinline__ void cvtA_store8(float4 va, float4 vb, float sc,
                                            uint32_t hiAddr, uint32_t loAddr) {
    va.x *= sc; va.y *= sc; va.z *= sc; va.w *= sc;
    vb.x *= sc; vb.y *= sc; vb.z *= sc; vb.w *= sc;
    __half2 h0 = __float22half2_rn(make_float2(va.x, va.y));
    __half2 h1 = __float22half2_rn(make_float2(va.z, va.w));
    __half2 h2 = __float22half2_rn(make_float2(vb.x, vb.y));
    __half2 h3 = __float22half2_rn(make_float2(vb.z, vb.w));
    float2 f0 = __half22float2(h0);
    float2 f1 = __half22float2(h1);
    float2 f2 = __half22float2(h2);
    float2 f3 = __half22float2(h3);
    __half2 l0 = __float22half2_rn(make_float2(va.x - f0.x, va.y - f0.y));
    __half2 l1 = __float22half2_rn(make_float2(va.z - f1.x, va.w - f1.y));
    __half2 l2 = __float22half2_rn(make_float2(vb.x - f2.x, vb.y - f2.y));
    __half2 l3 = __float22half2_rn(make_float2(vb.z - f3.x, vb.w - f3.y));
    sts16(hiAddr, make_uint4(*(uint32_t*)&h0, *(uint32_t*)&h1, *(uint32_t*)&h2, *(uint32_t*)&h3));
    sts16(loAddr, make_uint4(*(uint32_t*)&l0, *(uint32_t*)&l1, *(uint32_t*)&l2, *(uint32_t*)&l3));
}

// ---------------- softmax ----------------
__global__ void softmax_kernel(const float* __restrict__ t1,
                               const float* __restrict__ t2,
                               const float* __restrict__ t3) {
    const float* src = (blockIdx.x == 0) ? t1 : (blockIdx.x == 1) ? t2 : t3;
    float* dst = (blockIdx.x == 0) ? g_c1 : (blockIdx.x == 1) ? g_c2 : g_c3;
    int l = threadIdx.x;
    float v[16];
    float mx = -1e30f;
#pragma unroll
    for (int k = 0; k < 16; k++) { v[k] = src[l*16 + k]; mx = fmaxf(mx, v[k]); }
    float s = 0.f;
#pragma unroll
    for (int k = 0; k < 16; k++) { v[k] = expf(v[k] - mx); s += v[k]; }
    float inv = 1.f / s;
#pragma unroll
    for (int k = 0; k < 16; k++) dst[l*16 + k] = v[k] * inv;
}

// ---------------- Gram ----------------
__global__ void gram_kernel(const float* __restrict__ Wg,
                            const float* __restrict__ Wu,
                            const float* __restrict__ Wd) {
    int w = blockIdx.y;
    const float* W; float* G; int R, C;
    if (w == 0)      { W = Wg; G = g_Gg; R = Dd; C = Ff; }
    else if (w == 1) { W = Wu; G = g_Gu; R = Dd; C = Ff; }
    else             { W = Wd; G = g_Gd; R = Ff; C = Dd; }
    int c0 = blockIdx.x * 32;
    if (c0 >= C) return;

    __shared__ __align__(16) float s[16][8][32];
    int t = threadIdx.x;
    int cc = t & 31;
    int pg = t >> 5;
    float acc[32];
#pragma unroll
    for (int i = 0; i < 32; i++) acc[i] = 0.f;

    for (int r0 = 0; r0 < R; r0 += 8) {
        __syncthreads();
#pragma unroll
        for (int j = 0; j < 16; j++) {
            int idx = j * 256 + t;
            int lc = idx & 31, rr = (idx >> 5) & 7, k = idx >> 8;
            s[k][rr][lc] = W[(size_t)k * R * C + (size_t)(r0 + rr) * C + c0 + lc];
        }
        __syncthreads();
#pragma unroll
        for (int rr = 0; rr < 8; rr++) {
            float wv[16];
#pragma unroll
            for (int k = 0; k < 16; k++) wv[k] = s[k][rr][cc];
            float a0 = s[(pg << 1) + 0][rr][cc];
            float a1 = s[(pg << 1) + 1][rr][cc];
#pragma unroll
            for (int pp = 0; pp < 16; pp++) acc[pp]      += a0 * wv[pp];
#pragma unroll
            for (int pp = 0; pp < 16; pp++) acc[16 + pp] += a1 * wv[pp];
        }
    }
#pragma unroll
    for (int pp = 0; pp < 32; pp++) {
        int p = ((pg << 1) + (pp >> 4)) * 16 + (pp & 15);
        G[(size_t)p * C + c0 + cc] = acc[pp];
    }
}

// ---------------- inverse norms: 8 tokens per block ----------------
__global__ void norm_kernel() {
    int w = blockIdx.z;
    int l0 = blockIdx.y * 8;
    const float* G; const float* coef; float* out; int C;
    if (w == 0)      { G = g_Gg; coef = g_c1; out = g_ing; C = Ff; }
    else if (w == 1) { G = g_Gu; coef = g_c2; out = g_inu; C = Ff; }
    else             { G = g_Gd; coef = g_c3; out = g_ind; C = Dd; }
    int c = blockIdx.x * 128 + threadIdx.x;
    if (c >= C) return;   // guard: down plane has C=512

    __shared__ float w2[8][256];
#pragma unroll
    for (int i = 0; i < 16; i++) {
        int idx = threadIdx.x * 16 + i;
        int li = idx >> 8, p = idx & 255;
        w2[li][p] = coef[(l0 + li) * 16 + (p >> 4)] * coef[(l0 + li) * 16 + (p & 15)];
    }
    __syncthreads();

    float acc[8];
#pragma unroll
    for (int i = 0; i < 8; i++) acc[i] = 0.f;
#pragma unroll 4
    for (int p = 0; p < 256; p++) {
        float g = G[(size_t)p * C + c];
#pragma unroll
        for (int i = 0; i < 8; i++) acc[i] += w2[i][p] * g;
    }
#pragma unroll
    for (int i = 0; i < 8; i++)
        out[(l0 + i) * C + c] = 1.f / fmaxf(sqrtf(fmaxf(acc[i], 0.f)), 1e-12f);
}

// ---------------- fp16 2-MMA GEMM: 512 threads, 16 warps, reg prefetch ----------------
// C[M=2048, Nglob] = A_eff @ Bw.  A_eff[m, kseg*Ka+d] = coef[(m&127)*16+kseg]*A[m,d].
// which==0: z=0 -> U (c1,x,Wg), z=1 -> V (c2,x,Wu). which==1: O (c3,h,Wd).
// BM=128, BK=32, warp grid 4m x 4n, warp tile 32 x (BN/4).
// Next-iter global loads issue BEFORE the MMA phase -> latency hidden by tensor work.
template<int BN>
__global__ void __launch_bounds__(512, 1) gemm7(
    const float* __restrict__ A0,
    const float* __restrict__ Bw0, const float* __restrict__ Bw1,
    int which, int Ka, int ksegShift, int Ktot, int Nglob)
{
    constexpr int WN = BN / 4;               // 64 / 16
    constexpr int NF = WN / 8;               // 8 / 2
    constexpr int AMB = 128 * 80;            // one A matrix (32 fp16 + pad)
    constexpr int BSTRIDE = BN * 2 + 16;     // 528 / 144
    constexpr int BMB = 32 * BSTRIDE;
    constexpr int QPT4 = BN / 64;            // float4 per thread for B (4 / 1)

    __shared__ __align__(128) char smem_raw[2 * AMB + BMB]; // 37376 / 25088
    uint32_t sA_hi = smem_u32(smem_raw);
    uint32_t sA_lo = sA_hi + AMB;
    uint32_t sB    = sA_hi + 2 * AMB;

    const float* coef; float* Cout; const float* Ap; const float* Bw;
    if (which == 0) {
        Ap = A0;
        if (blockIdx.z == 0) { coef = g_c1; Bw = Bw0; Cout = g_U; }
        else                 { coef = g_c2; Bw = Bw1; Cout = g_V; }
    } else {
        Ap = g_H; coef = g_c3; Bw = Bw0; Cout = g_O;
    }

    int t = threadIdx.x, lane = t & 31, warp = t >> 5;
    int wm = warp & 3, wn = warp >> 2;
    int m0 = blockIdx.y * 128, n0 = blockIdx.x * BN;

    // A staging: 4 threads per row, 8 floats each
    int arow = t >> 2, aq = t & 3;
    const float* aRow = Ap + (size_t)(m0 + arow) * Ka + aq * 8;
    const float* crow = coef + ((m0 + arow) & 127) * 16;
    uint32_t aoff = (uint32_t)arow * 80 + aq * 16;

    // B staging: 16 threads per k-row (32 rows), QPT4 float4 each, coalesced
    int krow = t >> 4;
    int bq = t & 15;
    const float* bRowBase = Bw + (size_t)krow * Nglob + n0;
    uint32_t bRowOff = (uint32_t)krow * BSTRIDE;

    float acc[2][NF][4];
#pragma unroll
    for (int f = 0; f < 2; f++)
#pragma unroll
        for (int g = 0; g < NF; g++)
#pragma unroll
            for (int j = 0; j < 4; j++) acc[f][g][j] = 0.f;

    int nit = Ktot >> 5;

    // prologue: load iter-0 tile into registers
    float4 pa0, pa1, pbv[QPT4];
    float psc;
    {
        psc = crow[0];
        pa0 = *(const float4*)(aRow + 0);
        pa1 = *(const float4*)(aRow + 4);
#pragma unroll
        for (int j = 0; j < QPT4; j++)
            pbv[j] = *(const float4*)(bRowBase + (bq + 16 * j) * 4);
    }

    for (int it = 0; it < nit; it++) {
        // ---- store registers -> smem (convert) ----
        cvtA_store8(pa0, pa1, psc, sA_hi + aoff, sA_lo + aoff);
#pragma unroll
        for (int j = 0; j < QPT4; j++)
            cvtB_store4(pbv[j], sB + bRowOff + (bq + 16 * j) * 8);
        __syncthreads();

        // ---- issue next-iter global loads (land during MMA) ----
        if (it + 1 < nit) {
            int ktn = (it + 1) << 5;
            psc = crow[ktn >> ksegShift];
            const float* ar = aRow + (ktn & (Ka - 1));
            pa0 = *(const float4*)(ar + 0);
            pa1 = *(const float4*)(ar + 4);
            const float* br = bRowBase + (size_t)ktn * Nglob;
#pragma unroll
            for (int j = 0; j < QPT4; j++)
                pbv[j] = *(const float4*)(br + (bq + 16 * j) * 4);
        }

        // ---- MMA: 2 k-steps of 16 ----
#pragma unroll
        for (int ks = 0; ks < 2; ks++) {
            uint32_t BF[NF][2];
            uint32_t brow = (uint32_t)(ks * 16 + (lane & 15)) * BSTRIDE;
#pragma unroll
            for (int j = 0; j < NF / 2; j++) {
                uint32_t coff = (uint32_t)(wn * WN + j * 16 + ((lane >> 4) & 1) * 8) * 2;
                uint32_t r[4];
                ldsm4t(r, sB + brow + coff);
                BF[2*j][0] = r[0]; BF[2*j][1] = r[1];
                BF[2*j+1][0] = r[2]; BF[2*j+1][1] = r[3];
            }
            uint32_t acolB = (uint32_t)ks * 32 + ((lane >> 4) & 1) * 16;
            // A-hi pass
            {
                uint32_t AF[2][4];
#pragma unroll
                for (int f = 0; f < 2; f++) {
                    uint32_t roff = (uint32_t)(wm * 32 + f * 16 + (lane & 15)) * 80 + acolB;
                    ldsm4(AF[f], sA_hi + roff);
                }
#pragma unroll
                for (int f = 0; f < 2; f++)
#pragma unroll
                    for (int g = 0; g < NF; g++)
                        mmaf16(acc[f][g], AF[f], BF[g]);
            }
            // A-lo pass
            {
                uint32_t AF[2][4];
#pragma unroll
                for (int f = 0; f < 2; f++) {
                    uint32_t roff = (uint32_t)(wm * 32 + f * 16 + (lane & 15)) * 80 + acolB;
                    ldsm4(AF[f], sA_lo + roff);
                }
#pragma unroll
                for (int f = 0; f < 2; f++)
#pragma unroll
                    for (int g = 0; g < NF; g++)
                        mmaf16(acc[f][g], AF[f], BF[g]);
            }
        }
        __syncthreads();
    }

    // epilogue
#pragma unroll
    for (int f = 0; f < 2; f++) {
#pragma unroll
        for (int g = 0; g < NF; g++) {
            int r0 = m0 + wm * 32 + f * 16 + (lane >> 2);
            int col = n0 + wn * WN + g * 8 + (lane & 3) * 2;
            float* p = Cout + (size_t)r0 * Nglob + col;
            *(float2*)p = make_float2(acc[f][g][0], acc[f][g][1]);
            *(float2*)(p + 8 * (size_t)Nglob) = make_float2(acc[f][g][2], acc[f][g][3]);
        }
    }
}

// ---------------- elementwise h ----------------
__global__ void h_kernel(const float* __restrict__ usp, const float* __restrict__ vsp) {
    const float SQRT_D = 22.62741699796952f;
    int i4 = blockIdx.x * blockDim.x + threadIdx.x;
    if (i4 >= Mm * Ff / 4) return;
    int m  = i4 >> 8;
    int f  = (i4 & 255) * 4;
    int l  = m & 127;

    float4 u  = *(const float4*)(g_U   + (size_t)m * Ff + f);
    float4 v  = *(const float4*)(g_V   + (size_t)m * Ff + f);
    float4 ig = *(const float4*)(g_ing + (size_t)l * Ff + f);
    float4 iu = *(const float4*)(g_inu + (size_t)l * Ff + f);
    float4 us = *(const float4*)(usp + f);
    float4 vs = *(const float4*)(vsp + f);

    float4 h;
    { float uu = u.x * ig.x, vv = v.x * iu.x; float zz = fabsf(vs.x) * SQRT_D * vv;
      h.x = (zz / (1.f + expf(-zz))) * (fabsf(us.x) * uu); }
    { float uu = u.y * ig.y, vv = v.y * iu.y; float zz = fabsf(vs.y) * SQRT_D * vv;
      h.y = (zz / (1.f + expf(-zz))) * (fabsf(us.y) * uu); }
    { float uu = u.z * ig.z, vv = v.z * iu.z; float zz = fabsf(vs.z) * SQRT_D * vv;
      h.z = (zz / (1.f + expf(-zz))) * (fabsf(us.z) * uu); }
    { float uu = u.w * ig.w, vv = v.w * iu.w; float zz = fabsf(vs.w) * SQRT_D * vv;
      h.w = (zz / (1.f + expf(-zz))) * (fabsf(us.w) * uu); }
    *(float4*)(g_H + (size_t)m * Ff + f) = h;
}

// ---------------- final normalize ----------------
__global__ void out_kernel(float* __restrict__ out) {
    int m = blockIdx.x;
    int t = threadIdx.x;
    int l = m & 127;

    float4 o  = *(const float4*)(g_O   + (size_t)m * Dd + t * 4);
    float4 iv = *(const float4*)(g_ind + (size_t)l * Dd + t * 4);
    o.x *= iv.x; o.y *= iv.y; o.z *= iv.z; o.w *= iv.w;

    float ss = o.x*o.x + o.y*o.y + o.z*o.z + o.w*o.w;
#pragma unroll
    for (int off = 16; off > 0; off >>= 1)
        ss += __shfl_xor_sync(0xffffffffu, ss, off);

    __shared__ float ws[4];
    if ((t & 31) == 0) ws[t >> 5] = ss;
    __syncthreads();
    float tot = ws[0] + ws[1] + ws[2] + ws[3];
    float sc = 1.f / fmaxf(sqrtf(tot), 1e-12f);

    o.x *= sc; o.y *= sc; o.z *= sc; o.w *= sc;
    *(float4*)(out + (size_t)m * Dd + t * 4) = o;
}

// ---------------- launch ----------------
extern "C" void kernel_launch(void* const* d_in, const int* in_sizes, int n_in,
                              void* d_out, int out_size) {
    const float* x   = (const float*)d_in[0];
    const float* Wg  = (const float*)d_in[1];
    const float* Wu  = (const float*)d_in[2];
    const float* Wd  = (const float*)d_in[3];
    const float* t1  = (const float*)d_in[4];
    const float* t2  = (const float*)d_in[5];
    const float* t3  = (const float*)d_in[6];
    const float* usp = (const float*)d_in[7];
    const float* vsp = (const float*)d_in[8];
    float* out = (float*)d_out;

    softmax_kernel<<<3, 128>>>(t1, t2, t3);
    gram_kernel<<<dim3(32, 3), 256>>>(Wg, Wu, Wd);
    norm_kernel<<<dim3(8, 16, 3), 128>>>();

    // U and V fused (z=0 -> U, z=1 -> V): BN=256, 128 blocks, 512 threads
    gemm7<256><<<dim3(4, 16, 2), 512>>>(x, Wg, Wu, 0, 512, 9, 8192, 1024);
    // h = silu(vs*v) * (us*u)
    h_kernel<<<2048, 256>>>(usp, vsp);
    // O = (c3 . h) @ Wd: BN=64, 128 blocks, 512 threads
    gemm7<64><<<dim3(8, 16, 1), 512>>>(nullptr, Wd, nullptr, 1, 1024, 10, 16384, 512);
    // final
    out_kernel<<<2048, 128>>>(out);
}